// round 2
// baseline (speedup 1.0000x reference)
#include <cuda_runtime.h>
#include <math.h>

#define VOCAB   50257
#define DIM     512
#define MAXDEP  20
#define NTOK    8192          // B*S = 8*1024
#define NBLOCK  (NTOK / 8)    // 8 warps (tokens) per 256-thread block

// Scratch (allocation-free per harness rules).
__device__ float        g_partials[NBLOCK];
__device__ unsigned int g_count = 0;   // self-resets each launch -> graph-safe

__global__ void __launch_bounds__(256) hs_fused_kernel(
    const float* __restrict__ hidden,      // [NTOK, DIM]
    const float* __restrict__ node_emb,    // [VOCAB-1, DIM]
    const float* __restrict__ path_signs,  // [VOCAB, MAXDEP]
    const int*   __restrict__ targets,     // [NTOK]
    const int*   __restrict__ path_nodes,  // [VOCAB, MAXDEP]
    const int*   __restrict__ path_lens,   // [VOCAB]
    float*       __restrict__ out)
{
    __shared__ float s_warp[8];

    const int warp  = threadIdx.x >> 5;
    const int lane  = threadIdx.x & 31;
    const int gwarp = blockIdx.x * 8 + warp;   // token index

    const int t   = targets[gwarp];
    int       len = path_lens[t];
    if (len < 1) len = 1;

    // Coalesced per-lane preload of this token's path metadata, broadcast later.
    int   my_node = 0;
    float my_sign = 1.0f;
    if (lane < MAXDEP) {
        my_node = path_nodes[(size_t)t * MAXDEP + lane];
        my_sign = (path_signs[(size_t)t * MAXDEP + lane] >= 0.0f) ? 1.0f : -1.0f;
    }

    // Hidden row in registers: 16 floats/lane, coalesced.
    const float4* h4 = reinterpret_cast<const float4*>(hidden + (size_t)gwarp * DIM);
    const float4 h0 = h4[lane];
    const float4 h1 = h4[lane + 32];
    const float4 h2 = h4[lane + 64];
    const float4 h3 = h4[lane + 96];

    float nll = 0.0f;

    #pragma unroll 4
    for (int d = 0; d < MAXDEP; ++d) {
        if (d < len) {
            const int node = __shfl_sync(0xffffffffu, my_node, d);
            const float4* w4 =
                reinterpret_cast<const float4*>(node_emb + (size_t)node * DIM);
            const float4 w0 = w4[lane];
            const float4 w1 = w4[lane + 32];
            const float4 w2 = w4[lane + 64];
            const float4 w3 = w4[lane + 96];

            float acc;
            acc = h0.x * w0.x;            acc = fmaf(h0.y, w0.y, acc);
            acc = fmaf(h0.z, w0.z, acc);  acc = fmaf(h0.w, w0.w, acc);
            acc = fmaf(h1.x, w1.x, acc);  acc = fmaf(h1.y, w1.y, acc);
            acc = fmaf(h1.z, w1.z, acc);  acc = fmaf(h1.w, w1.w, acc);
            acc = fmaf(h2.x, w2.x, acc);  acc = fmaf(h2.y, w2.y, acc);
            acc = fmaf(h2.z, w2.z, acc);  acc = fmaf(h2.w, w2.w, acc);
            acc = fmaf(h3.x, w3.x, acc);  acc = fmaf(h3.y, w3.y, acc);
            acc = fmaf(h3.z, w3.z, acc);  acc = fmaf(h3.w, w3.w, acc);

            #pragma unroll
            for (int off = 16; off > 0; off >>= 1)
                acc += __shfl_xor_sync(0xffffffffu, acc, off);

            const float s = __shfl_sync(0xffffffffu, my_sign, d);
            const float z = s * acc;
            // -log sigmoid(z) = max(-z, 0) + log1p(exp(-|z|))   (stable)
            nll += fmaxf(-z, 0.0f) + log1pf(expf(-fabsf(z)));
        }
    }

    if (lane == 0) s_warp[warp] = nll;
    __syncthreads();

    // Thread 0 reduces the 8 warp sums, publishes the block partial.
    if (threadIdx.x == 0) {
        float bs = 0.0f;
        #pragma unroll
        for (int i = 0; i < 8; ++i) bs += s_warp[i];
        g_partials[blockIdx.x] = bs;
    }
    __threadfence();

    // Last-block-done pattern: one block deterministically reduces all partials.
    __shared__ unsigned int s_last;
    if (threadIdx.x == 0)
        s_last = (atomicAdd(&g_count, 1u) == (unsigned)(gridDim.x - 1));
    __syncthreads();

    if (s_last) {
        // 256 threads read 1024 partials (4 each), fixed-order tree reduce.
        float s = 0.0f;
        #pragma unroll
        for (int i = 0; i < NBLOCK / 256; ++i)
            s += g_partials[threadIdx.x + i * 256];

        __shared__ float sm[256];
        sm[threadIdx.x] = s;
        __syncthreads();
        #pragma unroll
        for (int k = 128; k > 0; k >>= 1) {
            if (threadIdx.x < k) sm[threadIdx.x] += sm[threadIdx.x + k];
            __syncthreads();
        }
        if (threadIdx.x == 0) {
            out[0]  = sm[0] * (1.0f / (float)NTOK);
            g_count = 0;   // reset for next launch / graph replay
        }
    }
}

extern "C" void kernel_launch(void* const* d_in, const int* in_sizes, int n_in,
                              void* d_out, int out_size)
{
    const float* hidden     = (const float*)d_in[0];
    const float* node_emb   = (const float*)d_in[1];
    const float* path_signs = (const float*)d_in[2];
    const int*   targets    = (const int*)  d_in[3];
    const int*   path_nodes = (const int*)  d_in[4];
    const int*   path_lens  = (const int*)  d_in[5];
    float*       out        = (float*)d_out;

    hs_fused_kernel<<<NBLOCK, 256>>>(hidden, node_emb, path_signs,
                                     targets, path_nodes, path_lens, out);
}